// round 9
// baseline (speedup 1.0000x reference)
#include <cuda_runtime.h>

// FlowNet2 Resample2d (kernel_size=1) bilinear warp.
// input1: [B, C, H, W] float, input2 (flow): [B, 2, H, W] float
//
// Structure locked from R6 (best: 64x4 tiles, scalar gathers; vector loads,
// smem staging, lockstep barriers, 32x8 tiles, stcg all proven non-wins).
// R9 change: unroll 8 with a 40-reg budget (launch_bounds 256,6) to deepen
// the software pipeline — batch ~2x the gather loads ahead of consumption,
// covering the L2/DRAM refill latency that leaves L1 ~16% idle.

#define BB 8
#define CC 32
#define HH 512
#define WW 512
#define HWSZ (HH * WW)   // 2^18

__global__ __launch_bounds__(256, 6)
void resample2d_kernel(const float* __restrict__ in1,
                       const float* __restrict__ flow,
                       float* __restrict__ out) {
    // Block tile: 64 px wide x 4 rows. Grid = 8 x-chunks * 128 y-chunks * 8 b.
    int blk = blockIdx.x;
    int x0 = (blk & 7) << 6;            // x-chunk * 64
    int y0 = ((blk >> 3) & 127) << 2;   // y-chunk * 4
    int b  = blk >> 10;                 // batch

    int w = x0 + (threadIdx.x & 63);
    int h = y0 + (threadIdx.x >> 6);
    int hw = (h << 9) | w;

    const float* fl = flow + ((size_t)b << 19); // b * 2 * HWSZ
    float dx = __ldg(fl + hw);
    float dy = __ldg(fl + HWSZ + hw);

    float xf = (float)w + dx;
    float yf = (float)h + dy;
    float x0f = floorf(xf);
    float y0f = floorf(yf);
    float alpha = xf - x0f;   // unclamped fractional weights
    float beta  = yf - y0f;

    int ix0 = (int)x0f;
    int iy0 = (int)y0f;
    int xL = min(max(ix0,     0), WW - 1);
    int xR = min(max(ix0 + 1, 0), WW - 1);
    int yT = min(max(iy0,     0), HH - 1);
    int yB = min(max(iy0 + 1, 0), HH - 1);

    float wTR = alpha * (1.0f - beta);
    float wBL = (1.0f - alpha) * beta;
    float wBR = alpha * beta;
    float wTL = 1.0f - wTR - wBL - wBR;

    const float* base = in1 + ((size_t)b << 23);   // b * C * HWSZ
    const float* pTL = base + ((yT << 9) + xL);
    const float* pTR = base + ((yT << 9) + xR);
    const float* pBL = base + ((yB << 9) + xL);
    const float* pBR = base + ((yB << 9) + xR);
    float* op = out + ((size_t)b << 23) + hw;

    #pragma unroll 8
    for (int c = 0; c < CC; c++) {
        int off = c << 18;   // c * HWSZ
        float v = wTL * __ldg(pTL + off)
                + wTR * __ldg(pTR + off)
                + wBL * __ldg(pBL + off)
                + wBR * __ldg(pBR + off);
        op[off] = v;
    }
}

extern "C" void kernel_launch(void* const* d_in, const int* in_sizes, int n_in,
                              void* d_out, int out_size) {
    const float* input1 = (const float*)d_in[0];
    const float* input2 = (const float*)d_in[1];
    float* out = (float*)d_out;

    const int blocks = 8 * 128 * BB;   // 8192 tiles of 64x4
    resample2d_kernel<<<blocks, 256>>>(input1, input2, out);
}